// round 5
// baseline (speedup 1.0000x reference)
#include <cuda_runtime.h>
#include <cstdint>

#define MAXN 100000
#define D 64
#define TN 128            // nodes per node-kernel tile
#define KD 192            // concatenated K dim: [x | A_O-cO x | A_I-cI x]
#define UTS 132           // Ut row stride (floats): 128 + 4 pad

// Scratch: [2][N][64] float accumulators (sum of x[src] per (half, dst)) + counts.
// Zero-initialized at module load; node_kernel re-zeroes after consuming, so the
// "zeroed at entry" invariant holds for every kernel_launch call (graph-safe).
__device__ float g_acc[2UL * MAXN * D];
__device__ int   g_cnt[2 * MAXN];

// ---------------------------------------------------------------------------
// One work item per (edge, float4-chunk): 16 threads cooperate per edge.
__global__ void scatter_kernel(const float* __restrict__ x,
                               const int* __restrict__ src,
                               const int* __restrict__ dst,
                               int E, int half, int n) {
    long gid = (long)blockIdx.x * blockDim.x + threadIdx.x;
    if (gid >= (long)E * 16) return;
    int e = (int)(gid >> 4);
    int j = (int)(gid & 15);
    int s = __ldg(src + e);
    int d = __ldg(dst + e);
    int hsel = (e >= half) ? 1 : 0;

    float4 v = __ldg(reinterpret_cast<const float4*>(x + (size_t)s * D) + j);
    float* p = g_acc + ((size_t)hsel * n + d) * D + j * 4;
    asm volatile("red.global.add.v4.f32 [%0], {%1,%2,%3,%4};"
                 :: "l"(p), "f"(v.x), "f"(v.y), "f"(v.z), "f"(v.w)
                 : "memory");
    if (j == 0) atomicAdd(&g_cnt[hsel * n + d], 1);
}

// ---------------------------------------------------------------------------
// FFMA2 helpers (packed f32x2 — only reachable via PTX fma.rn.f32x2)
__device__ __forceinline__ unsigned long long pack_dup(float a) {
    unsigned long long r;
    asm("mov.b64 %0, {%1, %1};" : "=l"(r) : "f"(a));
    return r;
}
__device__ __forceinline__ void ffma2(unsigned long long& acc,
                                      unsigned long long a,
                                      unsigned long long b) {
    asm("fma.rn.f32x2 %0, %1, %2, %0;" : "+l"(acc) : "l"(a), "l"(b));
}
__device__ __forceinline__ void unpack2(unsigned long long v, float& lo, float& hi) {
    asm("mov.b64 {%0, %1}, %2;" : "=f"(lo), "=f"(hi) : "l"(v));
}

// ---------------------------------------------------------------------------
// Node kernel: out[n] = U[n] @ Wcat^T + K + cO*bO + cI*bI
//   U[n] = [ x[n] | A_O[n]-cO x[n] | A_I[n]-cI x[n] ]  (192 wide, stored k-major)
//   Wcat = [ W_S ; W_O ; W_I ]                         (64 x 192)
//   K[d] = b_S[d] - r . W_S[d]
// Block: 128 threads, tile 128 nodes x 64 outs, thread = 8 nodes x 8 outs (f32x2).
// Last block (blockIdx.x == gridDim.x-1) computes r_out instead.
// Also re-zeroes g_acc / g_cnt after reading (replaces zero_kernel).
__global__ void node_kernel(const float* __restrict__ x,
                            const float* __restrict__ r,
                            const float* __restrict__ W_O, const float* __restrict__ b_O,
                            const float* __restrict__ W_I, const float* __restrict__ b_I,
                            const float* __restrict__ W_S, const float* __restrict__ b_S,
                            const float* __restrict__ W_R, const float* __restrict__ b_R,
                            float* __restrict__ out, int n) {
    int tid = threadIdx.x;

    // ---- r_out block ----
    if (blockIdx.x == gridDim.x - 1) {
        if (tid < 64) {
            float acc = b_R[tid];
            const float* wrow = W_R + tid * 64;
            #pragma unroll 8
            for (int k = 0; k < 64; k++) acc += r[k] * wrow[k];
            out[(size_t)n * D + tid] = acc;
        }
        return;
    }

    extern __shared__ float sm[];
    float* Ut  = sm;                    // [192][UTS]   Ut[k][node]
    float* WT  = Ut + KD * UTS;         // [192][64]    WT[k][d] = Wcat[d][k]
    float* Ksm = WT + KD * 64;          // [64]
    float* bOs = Ksm + 64;              // [64]
    float* bIs = bOs + 64;              // [64]
    float* cOs = bIs + 64;              // [128]
    float* cIs = cOs + TN;              // [128]

    int node0 = blockIdx.x * TN;

    // ---- stage transposed weights: seg0=W_S, seg1=W_O, seg2=W_I ----
    {
        int dd = tid & 63;
        int q0 = tid >> 6;  // 0..1
        const float* Ws[3] = { W_S, W_O, W_I };
        #pragma unroll
        for (int m = 0; m < 3; m++) {
            const float* W = Ws[m];
            for (int q = q0; q < 16; q += 2) {
                float4 w = __ldg(reinterpret_cast<const float4*>(W + dd * 64) + q);
                int kb = m * 64 + q * 4;
                WT[(kb + 0) * 64 + dd] = w.x;
                WT[(kb + 1) * 64 + dd] = w.y;
                WT[(kb + 2) * 64 + dd] = w.z;
                WT[(kb + 3) * 64 + dd] = w.w;
            }
        }
    }

    // ---- constants / biases ----
    if (tid < 64) {
        float acc = b_S[tid];
        const float* wrow = W_S + tid * 64;
        #pragma unroll 8
        for (int k = 0; k < 64; k++) acc -= r[k] * wrow[k];
        Ksm[tid] = acc;
        bOs[tid] = b_O[tid];
        bIs[tid] = b_I[tid];
    }

    // ---- stage U (transposed into Ut), fixup -c*x, and re-zero scratch ----
    {
        int nl = tid;             // this thread owns node nl of the tile
        int nn = node0 + nl;
        float cO = 0.f, cI = 0.f;
        if (nn < n) {
            cO = (float)g_cnt[nn];
            cI = (float)g_cnt[n + nn];
            g_cnt[nn] = 0;
            g_cnt[n + nn] = 0;
        }
        cOs[nl] = cO;
        cIs[nl] = cI;

        const float4 z4 = make_float4(0.f, 0.f, 0.f, 0.f);
        float4* accO = reinterpret_cast<float4*>(g_acc + (size_t)nn * D);
        float4* accI = reinterpret_cast<float4*>(g_acc + ((size_t)n + nn) * D);
        const float4* xr = reinterpret_cast<const float4*>(x + (size_t)nn * D);

        #pragma unroll 4
        for (int q = 0; q < 16; q++) {
            float4 vx = z4, vo = z4, vi = z4;
            if (nn < n) {
                vx = __ldg(xr + q);
                vo = accO[q];
                vi = accI[q];
                accO[q] = z4;        // restore zero invariant
                accI[q] = z4;
            }
            vo.x -= cO * vx.x; vo.y -= cO * vx.y; vo.z -= cO * vx.z; vo.w -= cO * vx.w;
            vi.x -= cI * vx.x; vi.y -= cI * vx.y; vi.z -= cI * vx.z; vi.w -= cI * vx.w;
            int k0 = q * 4;
            Ut[(k0 + 0) * UTS + nl] = vx.x;
            Ut[(k0 + 1) * UTS + nl] = vx.y;
            Ut[(k0 + 2) * UTS + nl] = vx.z;
            Ut[(k0 + 3) * UTS + nl] = vx.w;
            Ut[(64 + k0 + 0) * UTS + nl] = vo.x;
            Ut[(64 + k0 + 1) * UTS + nl] = vo.y;
            Ut[(64 + k0 + 2) * UTS + nl] = vo.z;
            Ut[(64 + k0 + 3) * UTS + nl] = vo.w;
            Ut[(128 + k0 + 0) * UTS + nl] = vi.x;
            Ut[(128 + k0 + 1) * UTS + nl] = vi.y;
            Ut[(128 + k0 + 2) * UTS + nl] = vi.z;
            Ut[(128 + k0 + 3) * UTS + nl] = vi.w;
        }
    }
    __syncthreads();

    // ---- main GEMM: thread = 8 nodes x 8 outs, packed f32x2 FMA ----
    int tx = tid & 7;        // out octet: outs tx*8 .. tx*8+7
    int ty = tid >> 3;       // node octet: nodes ty*8 .. ty*8+7

    unsigned long long acc[8][4];
    #pragma unroll
    for (int i = 0; i < 8; i++)
        #pragma unroll
        for (int j = 0; j < 4; j++) acc[i][j] = 0ULL;

    const float* Abase = Ut + ty * 8;
    const float* Bbase = WT + tx * 8;

    #pragma unroll 4
    for (int k = 0; k < KD; k++) {
        float4 a0 = *reinterpret_cast<const float4*>(Abase + k * UTS);
        float4 a1 = *reinterpret_cast<const float4*>(Abase + k * UTS + 4);
        ulonglong2 b01 = *reinterpret_cast<const ulonglong2*>(Bbase + k * 64);
        ulonglong2 b23 = *reinterpret_cast<const ulonglong2*>(Bbase + k * 64 + 4);

        unsigned long long aa[8];
        aa[0] = pack_dup(a0.x); aa[1] = pack_dup(a0.y);
        aa[2] = pack_dup(a0.z); aa[3] = pack_dup(a0.w);
        aa[4] = pack_dup(a1.x); aa[5] = pack_dup(a1.y);
        aa[6] = pack_dup(a1.z); aa[7] = pack_dup(a1.w);

        #pragma unroll
        for (int i = 0; i < 8; i++) {
            ffma2(acc[i][0], aa[i], b01.x);
            ffma2(acc[i][1], aa[i], b01.y);
            ffma2(acc[i][2], aa[i], b23.x);
            ffma2(acc[i][3], aa[i], b23.y);
        }
    }

    // ---- epilogue ----
    float kk[8], bo[8], bi[8];
    #pragma unroll
    for (int j = 0; j < 8; j++) {
        kk[j] = Ksm[tx * 8 + j];
        bo[j] = bOs[tx * 8 + j];
        bi[j] = bIs[tx * 8 + j];
    }
    #pragma unroll
    for (int i = 0; i < 8; i++) {
        int nl = ty * 8 + i;
        int nn = node0 + nl;
        if (nn >= n) continue;
        float cO = cOs[nl], cI = cIs[nl];
        float o[8];
        #pragma unroll
        for (int j = 0; j < 4; j++) {
            float lo, hi;
            unpack2(acc[i][j], lo, hi);
            o[2 * j]     = lo + kk[2 * j]     + cO * bo[2 * j]     + cI * bi[2 * j];
            o[2 * j + 1] = hi + kk[2 * j + 1] + cO * bo[2 * j + 1] + cI * bi[2 * j + 1];
        }
        float4* orow = reinterpret_cast<float4*>(out + (size_t)nn * D + tx * 8);
        orow[0] = make_float4(o[0], o[1], o[2], o[3]);
        orow[1] = make_float4(o[4], o[5], o[6], o[7]);
    }
}

// ---------------------------------------------------------------------------
extern "C" void kernel_launch(void* const* d_in, const int* in_sizes, int n_in,
                              void* d_out, int out_size) {
    const float* x   = (const float*)d_in[0];
    const float* r   = (const float*)d_in[1];
    const int*   src = (const int*)d_in[2];
    const int*   dst = (const int*)d_in[3];
    const float* W_O = (const float*)d_in[4];
    const float* b_O = (const float*)d_in[5];
    const float* W_I = (const float*)d_in[6];
    const float* b_I = (const float*)d_in[7];
    const float* W_S = (const float*)d_in[8];
    const float* b_S = (const float*)d_in[9];
    const float* W_R = (const float*)d_in[10];
    const float* b_R = (const float*)d_in[11];
    float* out = (float*)d_out;

    int n = in_sizes[0] / D;       // 100000
    int E = in_sizes[2];           // 1200000
    int half = E / 2;

    const int SMEM_BYTES = (KD * UTS + KD * 64 + 3 * 64 + 2 * TN) * sizeof(float);
    static bool attr_set = false;
    cudaFuncSetAttribute(node_kernel, cudaFuncAttributeMaxDynamicSharedMemorySize, SMEM_BYTES);
    (void)attr_set;

    long items = (long)E * 16;
    int sblocks = (int)((items + 255) / 256);
    scatter_kernel<<<sblocks, 256>>>(x, src, dst, E, half, n);

    int nblocks = (n + TN - 1) / TN + 1;   // +1 block for r_out
    node_kernel<<<nblocks, 128, SMEM_BYTES>>>(x, r, W_O, b_O, W_I, b_I, W_S, b_S,
                                              W_R, b_R, out, n);
}

// round 6
// speedup vs baseline: 3.5444x; 3.5444x over previous
#include <cuda_runtime.h>
#include <cstdint>

#define MAXN 100000
#define MAXE 1200000
#define D 64
#define UP 204            // padded U row stride (floats)
#define TILE_N 64
#define SCAN_BLK 1024     // bins per scan block

// Scratch
__device__ float g_acc[2UL * MAXN * D];   // gather results [2][N][64]
__device__ int   g_cnt[2 * MAXN];         // per-(half,node) degree (histogram)
__device__ int   g_off[2 * MAXN];         // exclusive-scan offsets
__device__ int   g_cur[2 * MAXN];         // placement cursors
__device__ int   g_eidx[MAXE];            // CSR: src index per edge slot
__device__ int   g_bsum[256];             // scan block sums
__device__ int   g_bbase[256];            // scanned block bases

// ---------------------------------------------------------------------------
__global__ void zero_small(int nb2) {
    int i = blockIdx.x * blockDim.x + threadIdx.x;
    if (i < nb2) { g_cnt[i] = 0; g_cur[i] = 0; }
}

// ---------------------------------------------------------------------------
__global__ void hist_kernel(const int* __restrict__ dst, int E, int half, int n) {
    int e = blockIdx.x * blockDim.x + threadIdx.x;
    if (e >= E) return;
    int d = __ldg(dst + e);
    int bin = (e >= half) ? (n + d) : d;
    atomicAdd(&g_cnt[bin], 1);
}

// ---------------------------------------------------------------------------
// scanA: per-block exclusive scan of 1024 bins; block total -> g_bsum
__global__ void scanA(int nb2) {
    __shared__ int warp_sums[8];
    __shared__ int wbase[8];
    int t = threadIdx.x;
    int base = blockIdx.x * SCAN_BLK;
    int idx0 = base + t * 4;
    int v[4];
    #pragma unroll
    for (int j = 0; j < 4; j++) {
        int i = idx0 + j;
        v[j] = (i < nb2) ? g_cnt[i] : 0;
    }
    int s = v[0] + v[1] + v[2] + v[3];
    int lane = t & 31, wid = t >> 5;
    int sc = s;
    #pragma unroll
    for (int o = 1; o < 32; o <<= 1) {
        int u = __shfl_up_sync(0xFFFFFFFFu, sc, o);
        if (lane >= o) sc += u;
    }
    if (lane == 31) warp_sums[wid] = sc;
    __syncthreads();
    if (t == 0) {
        int run = 0;
        #pragma unroll
        for (int w = 0; w < 8; w++) { wbase[w] = run; run += warp_sums[w]; }
        g_bsum[blockIdx.x] = run;
    }
    __syncthreads();
    int run = wbase[wid] + (sc - s);   // exclusive prefix for this thread's quad
    #pragma unroll
    for (int j = 0; j < 4; j++) {
        int i = idx0 + j;
        if (i < nb2) g_off[i] = run;
        run += v[j];
    }
}

// scanB: single block scans block sums -> g_bbase (exclusive)
__global__ void scanB(int nblk) {
    __shared__ int sm[256];
    int t = threadIdx.x;
    int v = (t < nblk) ? g_bsum[t] : 0;
    sm[t] = v;
    __syncthreads();
    for (int o = 1; o < 256; o <<= 1) {
        int u = (t >= o) ? sm[t - o] : 0;
        __syncthreads();
        sm[t] += u;
        __syncthreads();
    }
    g_bbase[t] = sm[t] - v;
}

// scanC: add block bases
__global__ void scanC(int nb2) {
    int t = threadIdx.x;
    int base = blockIdx.x * SCAN_BLK;
    int add = g_bbase[blockIdx.x];
    #pragma unroll
    for (int j = 0; j < 4; j++) {
        int i = base + t * 4 + j;
        if (i < nb2) g_off[i] += add;
    }
}

// ---------------------------------------------------------------------------
__global__ void place_kernel(const int* __restrict__ src,
                             const int* __restrict__ dst,
                             int E, int half, int n) {
    int e = blockIdx.x * blockDim.x + threadIdx.x;
    if (e >= E) return;
    int s = __ldg(src + e);
    int d = __ldg(dst + e);
    int bin = (e >= half) ? (n + d) : d;
    int pos = atomicAdd(&g_cur[bin], 1);
    g_eidx[g_off[bin] + pos] = s;
}

// ---------------------------------------------------------------------------
// One warp per bin: sum x[src] rows over the bin's CSR list, write g_acc row.
// Lane l owns floats [2l, 2l+1] of the 64-wide row (float2, 256B coalesced).
__global__ void gather_kernel(const float* __restrict__ x, int nb2) {
    int wid_in_blk = threadIdx.x >> 5;
    int lane = threadIdx.x & 31;
    int bin = blockIdx.x * 8 + wid_in_blk;
    if (bin >= nb2) return;
    int deg = g_cnt[bin];
    int off = g_off[bin];

    float2 a = make_float2(0.f, 0.f);
    float2 b = make_float2(0.f, 0.f);
    int i = 0;
    for (; i + 1 < deg; i += 2) {
        int s0 = __ldg(g_eidx + off + i);
        int s1 = __ldg(g_eidx + off + i + 1);
        float2 v0 = __ldg(reinterpret_cast<const float2*>(x + (size_t)s0 * D) + lane);
        float2 v1 = __ldg(reinterpret_cast<const float2*>(x + (size_t)s1 * D) + lane);
        a.x += v0.x; a.y += v0.y;
        b.x += v1.x; b.y += v1.y;
    }
    if (i < deg) {
        int s0 = __ldg(g_eidx + off + i);
        float2 v0 = __ldg(reinterpret_cast<const float2*>(x + (size_t)s0 * D) + lane);
        a.x += v0.x; a.y += v0.y;
    }
    a.x += b.x; a.y += b.y;
    reinterpret_cast<float2*>(g_acc + (size_t)bin * D)[lane] = a;
}

// ---------------------------------------------------------------------------
// Node kernel (proven R4 form): out[n] = U[n] @ Wcat^T + K + cO*bO + cI*bI
// Last block computes r_out.
__global__ void node_kernel(const float* __restrict__ x,
                            const float* __restrict__ r,
                            const float* __restrict__ W_O, const float* __restrict__ b_O,
                            const float* __restrict__ W_I, const float* __restrict__ b_I,
                            const float* __restrict__ W_S, const float* __restrict__ b_S,
                            const float* __restrict__ W_R, const float* __restrict__ b_R,
                            float* __restrict__ out, int n) {
    int tid = threadIdx.x;

    if (blockIdx.x == gridDim.x - 1) {   // r_out block
        if (tid < 64) {
            float acc = b_R[tid];
            const float* wrow = W_R + tid * 64;
            #pragma unroll 8
            for (int k = 0; k < 64; k++) acc += r[k] * wrow[k];
            out[(size_t)n * D + tid] = acc;
        }
        return;
    }

    extern __shared__ float sm[];
    float* WT  = sm;                    // [192][64]
    float* U   = WT + 192 * 64;         // [64][UP]
    float* Ksm = U + 64 * UP;           // [64]
    float* bOs = Ksm + 64;
    float* bIs = bOs + 64;
    float* cOs = bIs + 64;
    float* cIs = cOs + 64;

    int node0 = blockIdx.x * TILE_N;

    // stage transposed weights
    {
        int dd = tid & 63;
        int q0 = tid >> 6;
        const float* Ws[3] = { W_S, W_O, W_I };
        #pragma unroll
        for (int m = 0; m < 3; m++) {
            const float* W = Ws[m];
            for (int q = q0; q < 16; q += 4) {
                float4 w = __ldg(reinterpret_cast<const float4*>(W + dd * 64) + q);
                int kb = m * 64 + q * 4;
                WT[(kb + 0) * 64 + dd] = w.x;
                WT[(kb + 1) * 64 + dd] = w.y;
                WT[(kb + 2) * 64 + dd] = w.z;
                WT[(kb + 3) * 64 + dd] = w.w;
            }
        }
    }

    if (tid < 64) {
        float acc = b_S[tid];
        const float* wrow = W_S + tid * 64;
        #pragma unroll 8
        for (int k = 0; k < 64; k++) acc -= r[k] * wrow[k];
        Ksm[tid] = acc;
        bOs[tid] = b_O[tid];
        bIs[tid] = b_I[tid];
        int nn = node0 + tid;
        cOs[tid] = (nn < n) ? (float)g_cnt[nn] : 0.f;
        cIs[tid] = (nn < n) ? (float)g_cnt[n + nn] : 0.f;
    }

    // stage raw U = [x | A_O | A_I]
    {
        int kq  = tid & 15;
        int nl0 = tid >> 4;
        for (int nl = nl0; nl < TILE_N; nl += 16) {
            int nn = node0 + nl;
            float4 vx = make_float4(0, 0, 0, 0), vo = vx, vi = vx;
            if (nn < n) {
                vx = __ldg(reinterpret_cast<const float4*>(x + (size_t)nn * D) + kq);
                vo = *(reinterpret_cast<const float4*>(g_acc + (size_t)nn * D) + kq);
                vi = *(reinterpret_cast<const float4*>(g_acc + ((size_t)n + nn) * D) + kq);
            }
            float4* Ur = reinterpret_cast<float4*>(U + nl * UP);
            Ur[kq]      = vx;
            Ur[16 + kq] = vo;
            Ur[32 + kq] = vi;
        }
    }
    __syncthreads();

    // fixup: subtract count * x
    {
        int kq  = tid & 15;
        int nl0 = tid >> 4;
        for (int nl = nl0; nl < TILE_N; nl += 16) {
            float cO = cOs[nl], cI = cIs[nl];
            float4* Ur = reinterpret_cast<float4*>(U + nl * UP);
            float4 vx = Ur[kq];
            float4 vo = Ur[16 + kq];
            float4 vi = Ur[32 + kq];
            vo.x -= cO * vx.x; vo.y -= cO * vx.y; vo.z -= cO * vx.z; vo.w -= cO * vx.w;
            vi.x -= cI * vx.x; vi.y -= cI * vx.y; vi.z -= cI * vx.z; vi.w -= cI * vx.w;
            Ur[16 + kq] = vo;
            Ur[32 + kq] = vi;
        }
    }
    __syncthreads();

    // main GEMM: 4 nodes x 4 outputs per thread
    int tx = tid & 15;
    int ty = tid >> 4;
    const float* Brow = WT + tx * 4;
    const float* U0 = U + (ty * 4 + 0) * UP;
    const float* U1 = U0 + UP;
    const float* U2 = U1 + UP;
    const float* U3 = U2 + UP;

    float acc[4][4];
    #pragma unroll
    for (int i = 0; i < 4; i++)
        #pragma unroll
        for (int j = 0; j < 4; j++) acc[i][j] = 0.f;

    #pragma unroll 4
    for (int k = 0; k < 192; k++) {
        float4 b = *reinterpret_cast<const float4*>(Brow + k * 64);
        float a0 = U0[k], a1 = U1[k], a2 = U2[k], a3 = U3[k];
        acc[0][0] += a0 * b.x; acc[0][1] += a0 * b.y; acc[0][2] += a0 * b.z; acc[0][3] += a0 * b.w;
        acc[1][0] += a1 * b.x; acc[1][1] += a1 * b.y; acc[1][2] += a1 * b.z; acc[1][3] += a1 * b.w;
        acc[2][0] += a2 * b.x; acc[2][1] += a2 * b.y; acc[2][2] += a2 * b.z; acc[2][3] += a2 * b.w;
        acc[3][0] += a3 * b.x; acc[3][1] += a3 * b.y; acc[3][2] += a3 * b.z; acc[3][3] += a3 * b.w;
    }

    float k0 = Ksm[tx * 4 + 0], k1 = Ksm[tx * 4 + 1], k2 = Ksm[tx * 4 + 2], k3 = Ksm[tx * 4 + 3];
    float bo0 = bOs[tx * 4 + 0], bo1 = bOs[tx * 4 + 1], bo2 = bOs[tx * 4 + 2], bo3 = bOs[tx * 4 + 3];
    float bi0 = bIs[tx * 4 + 0], bi1 = bIs[tx * 4 + 1], bi2 = bIs[tx * 4 + 2], bi3 = bIs[tx * 4 + 3];
    #pragma unroll
    for (int i = 0; i < 4; i++) {
        int nl = ty * 4 + i;
        int nn = node0 + nl;
        if (nn >= n) continue;
        float cO = cOs[nl], cI = cIs[nl];
        float4 o;
        o.x = acc[i][0] + k0 + cO * bo0 + cI * bi0;
        o.y = acc[i][1] + k1 + cO * bo1 + cI * bi1;
        o.z = acc[i][2] + k2 + cO * bo2 + cI * bi2;
        o.w = acc[i][3] + k3 + cO * bo3 + cI * bi3;
        *(reinterpret_cast<float4*>(out + (size_t)nn * D) + tx) = o;
    }
}

// ---------------------------------------------------------------------------
extern "C" void kernel_launch(void* const* d_in, const int* in_sizes, int n_in,
                              void* d_out, int out_size) {
    const float* x   = (const float*)d_in[0];
    const float* r   = (const float*)d_in[1];
    const int*   src = (const int*)d_in[2];
    const int*   dst = (const int*)d_in[3];
    const float* W_O = (const float*)d_in[4];
    const float* b_O = (const float*)d_in[5];
    const float* W_I = (const float*)d_in[6];
    const float* b_I = (const float*)d_in[7];
    const float* W_S = (const float*)d_in[8];
    const float* b_S = (const float*)d_in[9];
    const float* W_R = (const float*)d_in[10];
    const float* b_R = (const float*)d_in[11];
    float* out = (float*)d_out;

    int n = in_sizes[0] / D;       // 100000
    int E = in_sizes[2];           // 1200000
    int half = E / 2;
    int nb2 = 2 * n;
    int nscan = (nb2 + SCAN_BLK - 1) / SCAN_BLK;   // 196

    const int SMEM_BYTES = (192 * 64 + 64 * UP + 5 * 64) * sizeof(float);
    cudaFuncSetAttribute(node_kernel, cudaFuncAttributeMaxDynamicSharedMemorySize, SMEM_BYTES);

    zero_small<<<(nb2 + 255) / 256, 256>>>(nb2);
    hist_kernel<<<(E + 255) / 256, 256>>>(dst, E, half, n);
    scanA<<<nscan, 256>>>(nb2);
    scanB<<<1, 256>>>(nscan);
    scanC<<<nscan, 256>>>(nb2);
    place_kernel<<<(E + 255) / 256, 256>>>(src, dst, E, half, n);
    gather_kernel<<<(nb2 + 7) / 8, 256>>>(x, nb2);

    int nblocks = (n + TILE_N - 1) / TILE_N + 1;   // +1 for r_out
    node_kernel<<<nblocks, 256, SMEM_BYTES>>>(x, r, W_O, b_O, W_I, b_I, W_S, b_S,
                                              W_R, b_R, out, n);
}

// round 7
// speedup vs baseline: 3.7571x; 1.0600x over previous
#include <cuda_runtime.h>
#include <cuda_bf16.h>
#include <cstdint>

#define MAXN 100000
#define MAXE 1200000
#define D 64
#define KD 192
#define MT 64             // node-tile rows per CTA (mma kernel)
#define US 200            // Uhi/Ulo row stride in bf16 (192 + 8 pad) -> 400B, conflict-free LDSM
#define WS 72             // WT row stride in bf16 (64 + 8 pad) -> 144B, conflict-free LDSM
#define SCAN_BLK 1024

// Scratch
__device__ float g_acc[2UL * MAXN * D];   // gather results [2][N][64]
__device__ int   g_cnt[2 * MAXN];         // per-(half,node) degree
__device__ int   g_off[2 * MAXN];         // exclusive-scan offsets
__device__ int   g_cur[2 * MAXN];         // placement cursors
__device__ int   g_eidx[MAXE];            // CSR: src index per edge slot
__device__ int   g_bsum[256];             // scan block sums

// ---------------------------------------------------------------------------
__global__ void zero_small(int nb2) {
    int i = blockIdx.x * blockDim.x + threadIdx.x;
    if (i < nb2) { g_cnt[i] = 0; g_cur[i] = 0; }
}

__global__ void hist_kernel(const int* __restrict__ dst, int E, int half, int n) {
    int e = blockIdx.x * blockDim.x + threadIdx.x;
    if (e >= E) return;
    int d = __ldg(dst + e);
    int bin = (e >= half) ? (n + d) : d;
    atomicAdd(&g_cnt[bin], 1);
}

// scanA: per-block exclusive scan of 1024 bins; block total -> g_bsum
__global__ void scanA(int nb2) {
    __shared__ int warp_sums[8];
    __shared__ int wbase[8];
    int t = threadIdx.x;
    int base = blockIdx.x * SCAN_BLK;
    int idx0 = base + t * 4;
    int v[4];
    #pragma unroll
    for (int j = 0; j < 4; j++) {
        int i = idx0 + j;
        v[j] = (i < nb2) ? g_cnt[i] : 0;
    }
    int s = v[0] + v[1] + v[2] + v[3];
    int lane = t & 31, wid = t >> 5;
    int sc = s;
    #pragma unroll
    for (int o = 1; o < 32; o <<= 1) {
        int u = __shfl_up_sync(0xFFFFFFFFu, sc, o);
        if (lane >= o) sc += u;
    }
    if (lane == 31) warp_sums[wid] = sc;
    __syncthreads();
    if (t == 0) {
        int run = 0;
        #pragma unroll
        for (int w = 0; w < 8; w++) { wbase[w] = run; run += warp_sums[w]; }
        g_bsum[blockIdx.x] = run;
    }
    __syncthreads();
    int run = wbase[wid] + (sc - s);
    #pragma unroll
    for (int j = 0; j < 4; j++) {
        int i = idx0 + j;
        if (i < nb2) g_off[i] = run;
        run += v[j];
    }
}

// scanC2: each block computes its own base (sum of preceding block sums) and adds it
__global__ void scanC2(int nb2, int nblk) {
    __shared__ int red[8];
    __shared__ int adds;
    int t = threadIdx.x;   // 256
    int b = blockIdx.x;
    int lane = t & 31, wid = t >> 5;
    int v = (t < b) ? g_bsum[t] : 0;
    #pragma unroll
    for (int o = 16; o > 0; o >>= 1) v += __shfl_down_sync(0xFFFFFFFFu, v, o);
    if (lane == 0) red[wid] = v;
    __syncthreads();
    if (t == 0) {
        int s = 0;
        #pragma unroll
        for (int w = 0; w < 8; w++) s += red[w];
        adds = s;
    }
    __syncthreads();
    int add = adds;
    int base = b * SCAN_BLK;
    #pragma unroll
    for (int j = 0; j < 4; j++) {
        int i = base + t * 4 + j;
        if (i < nb2) g_off[i] += add;
    }
}

__global__ void place_kernel(const int* __restrict__ src,
                             const int* __restrict__ dst,
                             int E, int half, int n) {
    int e = blockIdx.x * blockDim.x + threadIdx.x;
    if (e >= E) return;
    int s = __ldg(src + e);
    int d = __ldg(dst + e);
    int bin = (e >= half) ? (n + d) : d;
    int pos = atomicAdd(&g_cur[bin], 1);
    g_eidx[g_off[bin] + pos] = s;
}

// One warp per bin: sum x[src] rows, write g_acc row (no atomics).
__global__ void gather_kernel(const float* __restrict__ x, int nb2) {
    int wid_in_blk = threadIdx.x >> 5;
    int lane = threadIdx.x & 31;
    int bin = blockIdx.x * 8 + wid_in_blk;
    if (bin >= nb2) return;
    int deg = g_cnt[bin];
    int off = g_off[bin];

    float2 a = make_float2(0.f, 0.f);
    float2 b = make_float2(0.f, 0.f);
    int i = 0;
    for (; i + 1 < deg; i += 2) {
        int s0 = __ldg(g_eidx + off + i);
        int s1 = __ldg(g_eidx + off + i + 1);
        float2 v0 = __ldg(reinterpret_cast<const float2*>(x + (size_t)s0 * D) + lane);
        float2 v1 = __ldg(reinterpret_cast<const float2*>(x + (size_t)s1 * D) + lane);
        a.x += v0.x; a.y += v0.y;
        b.x += v1.x; b.y += v1.y;
    }
    if (i < deg) {
        int s0 = __ldg(g_eidx + off + i);
        float2 v0 = __ldg(reinterpret_cast<const float2*>(x + (size_t)s0 * D) + lane);
        a.x += v0.x; a.y += v0.y;
    }
    a.x += b.x; a.y += b.y;
    reinterpret_cast<float2*>(g_acc + (size_t)bin * D)[lane] = a;
}

// ---------------------------------------------------------------------------
// bf16 hi/lo split helpers
__device__ __forceinline__ void bsplit(float v, __nv_bfloat16& hi, __nv_bfloat16& lo) {
    hi = __float2bfloat16(v);
    lo = __float2bfloat16(v - __bfloat162float(hi));
}
__device__ __forceinline__ uint32_t sptr(const void* p) {
    return (uint32_t)__cvta_generic_to_shared(p);
}
__device__ __forceinline__ void ldsm_x4(uint32_t& r0, uint32_t& r1, uint32_t& r2, uint32_t& r3,
                                        uint32_t addr) {
    asm volatile("ldmatrix.sync.aligned.m8n8.x4.shared.b16 {%0,%1,%2,%3}, [%4];"
                 : "=r"(r0), "=r"(r1), "=r"(r2), "=r"(r3) : "r"(addr));
}
__device__ __forceinline__ void ldsm_x4_t(uint32_t& r0, uint32_t& r1, uint32_t& r2, uint32_t& r3,
                                          uint32_t addr) {
    asm volatile("ldmatrix.sync.aligned.m8n8.x4.trans.shared.b16 {%0,%1,%2,%3}, [%4];"
                 : "=r"(r0), "=r"(r1), "=r"(r2), "=r"(r3) : "r"(addr));
}
__device__ __forceinline__ void mma_bf16(float* c, uint32_t a0, uint32_t a1, uint32_t a2, uint32_t a3,
                                         uint32_t b0, uint32_t b1) {
    asm volatile("mma.sync.aligned.m16n8k16.row.col.f32.bf16.bf16.f32 "
                 "{%0,%1,%2,%3}, {%4,%5,%6,%7}, {%8,%9}, {%0,%1,%2,%3};"
                 : "+f"(c[0]), "+f"(c[1]), "+f"(c[2]), "+f"(c[3])
                 : "r"(a0), "r"(a1), "r"(a2), "r"(a3), "r"(b0), "r"(b1));
}

// ---------------------------------------------------------------------------
// Tensor-core node kernel.
//   out[n] = U[n] @ Wcat^T + K + cO*bO + cI*bI, U = [x | A_O-cO x | A_I-cI x]
// bf16 hi/lo split, 3 MMA passes: hi*hi + hi*lo + lo*hi (f32 accum).
// CTA: 128 threads (4 warps), tile MT=64 nodes x 64 outs. Warp = 16 rows.
// Last block computes r_out.
__global__ void node_mma_kernel(const float* __restrict__ x,
                                const float* __restrict__ r,
                                const float* __restrict__ W_O, const float* __restrict__ b_O,
                                const float* __restrict__ W_I, const float* __restrict__ b_I,
                                const float* __restrict__ W_S, const float* __restrict__ b_S,
                                const float* __restrict__ W_R, const float* __restrict__ b_R,
                                float* __restrict__ out, int n) {
    int tid = threadIdx.x;

    if (blockIdx.x == gridDim.x - 1) {   // r_out block
        if (tid < 64) {
            float acc = b_R[tid];
            const float* wrow = W_R + tid * 64;
            #pragma unroll 8
            for (int k = 0; k < 64; k++) acc += r[k] * wrow[k];
            out[(size_t)n * D + tid] = acc;
        }
        return;
    }

    extern __shared__ __align__(16) char smraw[];
    __nv_bfloat16* WThi = (__nv_bfloat16*)smraw;            // [192][WS]
    __nv_bfloat16* WTlo = WThi + KD * WS;                   // [192][WS]
    __nv_bfloat16* Uhi  = WTlo + KD * WS;                   // [MT][US]
    __nv_bfloat16* Ulo  = Uhi + MT * US;                    // [MT][US]
    float* Ksm = (float*)(Ulo + MT * US);                   // [64]
    float* bOs = Ksm + 64;
    float* bIs = bOs + 64;
    float* cOs = bIs + 64;                                  // [64]
    float* cIs = cOs + 64;                                  // [64]

    int node0 = blockIdx.x * MT;

    // ---- stage transposed split weights: WT[k][d], k-seg 0=W_S 1=W_O 2=W_I ----
    for (int idx = tid; idx < 3 * 64 * 16; idx += 128) {
        int m  = idx >> 10;          // 0..2
        int dq = idx & 1023;
        int d  = dq >> 4;            // 0..63
        int q  = dq & 15;            // 0..15
        const float* W = (m == 0) ? W_S : (m == 1) ? W_O : W_I;
        float4 w = __ldg(reinterpret_cast<const float4*>(W + d * 64) + q);
        int kb = m * 64 + q * 4;
        __nv_bfloat16 h, l;
        bsplit(w.x, h, l); WThi[(kb + 0) * WS + d] = h; WTlo[(kb + 0) * WS + d] = l;
        bsplit(w.y, h, l); WThi[(kb + 1) * WS + d] = h; WTlo[(kb + 1) * WS + d] = l;
        bsplit(w.z, h, l); WThi[(kb + 2) * WS + d] = h; WTlo[(kb + 2) * WS + d] = l;
        bsplit(w.w, h, l); WThi[(kb + 3) * WS + d] = h; WTlo[(kb + 3) * WS + d] = l;
    }

    // ---- constants / biases / counts (exact f32) ----
    if (tid < 64) {
        float acc = b_S[tid];
        const float* wrow = W_S + tid * 64;
        #pragma unroll 8
        for (int k = 0; k < 64; k++) acc -= r[k] * wrow[k];
        Ksm[tid] = acc;
        bOs[tid] = b_O[tid];
        bIs[tid] = b_I[tid];
        int nn = node0 + tid;
        cOs[tid] = (nn < n) ? (float)g_cnt[nn] : 0.f;
        cIs[tid] = (nn < n) ? (float)g_cnt[n + nn] : 0.f;
    }

    // ---- stage U tile (split into bf16 hi/lo): 2 threads per row ----
    {
        int nl = tid >> 1;           // 0..63
        int h  = tid & 1;            // half selector
        int nn = node0 + nl;
        float cO = 0.f, cI = 0.f;
        if (nn < n) {
            cO = (float)g_cnt[nn];
            cI = (float)g_cnt[n + nn];
        }
        const float4* xr = reinterpret_cast<const float4*>(x + (size_t)nn * D);
        const float4* ao = reinterpret_cast<const float4*>(g_acc + (size_t)nn * D);
        const float4* ai = reinterpret_cast<const float4*>(g_acc + ((size_t)n + nn) * D);
        __nv_bfloat162* UhiR = reinterpret_cast<__nv_bfloat162*>(Uhi + nl * US);
        __nv_bfloat162* UloR = reinterpret_cast<__nv_bfloat162*>(Ulo + nl * US);
        const float4 z4 = make_float4(0.f, 0.f, 0.f, 0.f);

        #pragma unroll
        for (int q = h * 8; q < h * 8 + 8; q++) {
            float4 vx = z4, vo = z4, vi = z4;
            if (nn < n) {
                vx = __ldg(xr + q);
                vo = ao[q];
                vi = ai[q];
            }
            vo.x -= cO * vx.x; vo.y -= cO * vx.y; vo.z -= cO * vx.z; vo.w -= cO * vx.w;
            vi.x -= cI * vx.x; vi.y -= cI * vx.y; vi.z -= cI * vx.z; vi.w -= cI * vx.w;
            int k2 = q * 2;   // bfloat162 index for k = q*4
            __nv_bfloat16 hx0, lx0, hx1, lx1;
            bsplit(vx.x, hx0, lx0); bsplit(vx.y, hx1, lx1);
            UhiR[k2]     = __nv_bfloat162(hx0, hx1);
            UloR[k2]     = __nv_bfloat162(lx0, lx1);
            bsplit(vx.z, hx0, lx0); bsplit(vx.w, hx1, lx1);
            UhiR[k2 + 1] = __nv_bfloat162(hx0, hx1);
            UloR[k2 + 1] = __nv_bfloat162(lx0, lx1);

            bsplit(vo.x, hx0, lx0); bsplit(vo.y, hx1, lx1);
            UhiR[32 + k2]     = __nv_bfloat162(hx0, hx1);
            UloR[32 + k2]     = __nv_bfloat162(lx0, lx1);
            bsplit(vo.z, hx0, lx0); bsplit(vo.w, hx1, lx1);
            UhiR[32 + k2 + 1] = __nv_bfloat162(hx0, hx1);
            UloR[32 + k2 + 1] = __nv_bfloat162(lx0, lx1);

            bsplit(vi.x, hx0, lx0); bsplit(vi.y, hx1, lx1);
            UhiR[64 + k2]     = __nv_bfloat162(hx0, hx1);
            UloR[64 + k2]     = __nv_bfloat162(lx0, lx1);
            bsplit(vi.z, hx0, lx0); bsplit(vi.w, hx1, lx1);
            UhiR[64 + k2 + 1] = __nv_bfloat162(hx0, hx1);
            UloR[64 + k2 + 1] = __nv_bfloat162(lx0, lx1);
        }
    }
    __syncthreads();

    // ---- MMA mainloop ----
    int warp = tid >> 5, lane = tid & 31;
    int wr0 = warp * 16;

    float acc[8][4];
    #pragma unroll
    for (int i = 0; i < 8; i++)
        #pragma unroll
        for (int j = 0; j < 4; j++) acc[i][j] = 0.f;

    // ldmatrix lane addressing: row = (lane&15), col-block = (lane>>4)*8
    int lrow = lane & 15;
    int lcol = (lane >> 4) * 8;
    uint32_t aHiBase = sptr(Uhi + (wr0 + lrow) * US + lcol);
    uint32_t aLoBase = sptr(Ulo + (wr0 + lrow) * US + lcol);
    uint32_t bHiBase = sptr(WThi + lrow * WS + lcol);
    uint32_t bLoBase = sptr(WTlo + lrow * WS + lcol);

    for (int ks = 0; ks < KD / 16; ks++) {
        uint32_t koffA = ks * 16 * 2;            // bytes into the row
        uint32_t koffB = (uint32_t)(ks * 16 * WS) * 2;   // bytes: 16 k-rows

        uint32_t ah0, ah1, ah2, ah3, al0, al1, al2, al3;
        ldsm_x4(ah0, ah1, ah2, ah3, aHiBase + koffA);
        ldsm_x4(al0, al1, al2, al3, aLoBase + koffA);

        uint32_t bh[4][4], bl[4][4];
        #pragma unroll
        for (int p = 0; p < 4; p++) {
            uint32_t cofs = (uint32_t)(p * 16) * 2;
            ldsm_x4_t(bh[p][0], bh[p][1], bh[p][2], bh[p][3], bHiBase + koffB + cofs);
            ldsm_x4_t(bl[p][0], bl[p][1], bl[p][2], bl[p][3], bLoBase + koffB + cofs);
        }

        #pragma unroll
        for (int p = 0; p < 4; p++) {
            mma_bf16(acc[2 * p],     ah0, ah1, ah2, ah3, bh[p][0], bh[p][1]);
            mma_bf16(acc[2 * p + 1], ah0, ah1, ah2, ah3, bh[p][2], bh[p][3]);
        }
        #pragma unroll
        for (int p = 0; p < 4; p++) {
            mma_bf16(acc[2 * p],     ah0, ah1, ah2, ah3, bl[p][0], bl[p][1]);
            mma_bf16(acc[2 * p + 1], ah0, ah1, ah2, ah3, bl[p][2], bl[p][3]);
        }
        #pragma unroll
        for (int p = 0; p < 4; p++) {
            mma_bf16(acc[2 * p],     al0, al1, al2, al3, bh[p][0], bh[p][1]);
            mma_bf16(acc[2 * p + 1], al0, al1, al2, al3, bh[p][2], bh[p][3]);
        }
    }

    // ---- epilogue: C frag rows = wr0 + lane/4 (+8), cols = nt*8 + (lane%4)*2 ----
    int rl0 = wr0 + (lane >> 2);
    int rl1 = rl0 + 8;
    int nn0 = node0 + rl0;
    int nn1 = node0 + rl1;
    float cO0 = cOs[rl0], cI0 = cIs[rl0];
    float cO1 = cOs[rl1], cI1 = cIs[rl1];
    int ecol = (lane & 3) * 2;

    #pragma unroll
    for (int nt = 0; nt < 8; nt++) {
        int c = nt * 8 + ecol;
        float k0v = Ksm[c],  k1v = Ksm[c + 1];
        float bo0 = bOs[c],  bo1 = bOs[c + 1];
        float bi0 = bIs[c],  bi1 = bIs[c + 1];
        if (nn0 < n) {
            float2 o;
            o.x = acc[nt][0] + k0v + cO0 * bo0 + cI0 * bi0;
            o.y = acc[nt][1] + k1v + cO0 * bo1 + cI0 * bi1;
            *reinterpret_cast<float2*>(out + (size_t)nn0 * D + c) = o;
        }
        if (nn1 < n) {
            float2 o;
            o.x = acc[nt][2] + k0v + cO1 * bo0 + cI1 * bi0;
            o.y = acc[nt][3] + k1v + cO1 * bo1 + cI1 * bi1;
            *reinterpret_cast<float2*>(out + (size_t)nn1 * D + c) = o;
        }
    }
}

// ---------------------------------------------------------------------------
extern "C" void kernel_launch(void* const* d_in, const int* in_sizes, int n_in,
                              void* d_out, int out_size) {
    const float* x   = (const float*)d_in[0];
    const float* r   = (const float*)d_in[1];
    const int*   src = (const int*)d_in[2];
    const int*   dst = (const int*)d_in[3];
    const float* W_O = (const float*)d_in[4];
    const float* b_O = (const float*)d_in[5];
    const float* W_I = (const float*)d_in[6];
    const float* b_I = (const float*)d_in[7];
    const float* W_S = (const float*)d_in[8];
    const float* b_S = (const float*)d_in[9];
    const float* W_R = (const float*)d_in[10];
    const float* b_R = (const float*)d_in[11];
    float* out = (float*)d_out;

    int n = in_sizes[0] / D;       // 100000
    int E = in_sizes[2];           // 1200000
    int half = E / 2;
    int nb2 = 2 * n;
    int nscan = (nb2 + SCAN_BLK - 1) / SCAN_BLK;   // 196

    const int SMEM_BYTES = (2 * KD * WS + 2 * MT * US) * (int)sizeof(__nv_bfloat16)
                         + 5 * 64 * (int)sizeof(float);      // 107,776 B
    cudaFuncSetAttribute(node_mma_kernel, cudaFuncAttributeMaxDynamicSharedMemorySize, SMEM_BYTES);

    zero_small<<<(nb2 + 255) / 256, 256>>>(nb2);
    hist_kernel<<<(E + 255) / 256, 256>>>(dst, E, half, n);
    scanA<<<nscan, 256>>>(nb2);
    scanC2<<<nscan, 256>>>(nb2, nscan);
    place_kernel<<<(E + 255) / 256, 256>>>(src, dst, E, half, n);
    gather_kernel<<<(nb2 + 7) / 8, 256>>>(x, nb2);

    int nblocks = (n + MT - 1) / MT + 1;   // +1 for r_out
    node_mma_kernel<<<nblocks, 128, SMEM_BYTES>>>(x, r, W_O, b_O, W_I, b_I, W_S, b_S,
                                                  W_R, b_R, out, n);
}

// round 9
// speedup vs baseline: 4.9480x; 1.3170x over previous
#include <cuda_runtime.h>
#include <cuda_bf16.h>
#include <cstdint>

#define MAXN 100000
#define MAXE 1200000
#define D 64
#define KD 192
#define MT 64             // node-tile rows per CTA (mma kernel)
#define US 200            // Uhi/Ulo row stride in bf16 (192 + 8 pad)
#define WS 72             // WT row stride in bf16 (64 + 8 pad)
#define SCAN_BLK 1024

// Scratch
__device__ float g_acc[2UL * MAXN * D];   // gather results [2][N][64]
__device__ int   g_cnt[2 * MAXN];         // per-(half,node) degree
__device__ int   g_off[2 * MAXN];         // scan offsets; after place: bin end
__device__ int   g_eidx[MAXE];            // CSR: src index per edge slot
__device__ int   g_bsum[256];             // scan block sums
__device__ __align__(16) __nv_bfloat16 g_wt[2 * KD * WS];  // [hi|lo] weight tiles
__device__ float g_const[192];            // [K(64) | bO(64) | bI(64)]

// ---------------------------------------------------------------------------
// Truncation bf16 split of a float pair -> packed hi (bf16x2) and lo (bf16x2).
__device__ __forceinline__ void tsplit2(float a, float b, uint32_t& hi, uint32_t& lo) {
    uint32_t ha = __float_as_uint(a) & 0xFFFF0000u;
    uint32_t hb = __float_as_uint(b) & 0xFFFF0000u;
    float la = a - __uint_as_float(ha);
    float lb = b - __uint_as_float(hb);
    hi = __byte_perm(ha, hb, 0x7632);
    lo = __byte_perm(__float_as_uint(la), __float_as_uint(lb), 0x7632);
}

// ---------------------------------------------------------------------------
// One-time prep: split weights into g_wt (node-kernel smem layout), consts.
__global__ void prep_kernel(const float* __restrict__ W_O, const float* __restrict__ W_I,
                            const float* __restrict__ W_S,
                            const float* __restrict__ b_O, const float* __restrict__ b_I,
                            const float* __restrict__ b_S, const float* __restrict__ r) {
    int b = blockIdx.x;
    int t = threadIdx.x;
    if (b < 3) {
        const float* W = (b == 0) ? W_S : (b == 1) ? W_O : W_I;
        unsigned short* gw = reinterpret_cast<unsigned short*>(g_wt);
        for (int idx = t; idx < 1024; idx += 256) {
            int d = idx >> 4, q = idx & 15;
            float4 w = __ldg(reinterpret_cast<const float4*>(W + d * 64) + q);
            int kb = b * 64 + q * 4;
            float vs[4] = { w.x, w.y, w.z, w.w };
            #pragma unroll
            for (int j = 0; j < 4; j++) {
                uint32_t h = __float_as_uint(vs[j]) & 0xFFFF0000u;
                float l = vs[j] - __uint_as_float(h);
                gw[(kb + j) * WS + d] = (unsigned short)(h >> 16);
                gw[KD * WS + (kb + j) * WS + d] = (unsigned short)(__float_as_uint(l) >> 16);
            }
        }
    } else {
        if (t < 64) {
            float acc = b_S[t];
            const float* wrow = W_S + t * 64;
            #pragma unroll 8
            for (int k = 0; k < 64; k++) acc -= r[k] * wrow[k];
            g_const[t] = acc;
        } else if (t < 128) {
            g_const[t] = b_O[t - 64];
        } else if (t < 192) {
            g_const[t] = b_I[t - 128];
        }
    }
}

// ---------------------------------------------------------------------------
__global__ void zero_small(int nb2) {
    int i = blockIdx.x * blockDim.x + threadIdx.x;
    if (i < nb2) g_cnt[i] = 0;
}

__global__ void hist_kernel(const int* __restrict__ dst, int E, int half, int n) {
    int e = blockIdx.x * blockDim.x + threadIdx.x;
    if (e >= E) return;
    int d = __ldg(dst + e);
    int bin = (e >= half) ? (n + d) : d;
    atomicAdd(&g_cnt[bin], 1);
}

// scanA: per-block exclusive scan of 1024 bins; block total -> g_bsum
__global__ void scanA(int nb2) {
    __shared__ int warp_sums[8];
    __shared__ int wbase[8];
    int t = threadIdx.x;
    int base = blockIdx.x * SCAN_BLK;
    int idx0 = base + t * 4;
    int v[4];
    #pragma unroll
    for (int j = 0; j < 4; j++) {
        int i = idx0 + j;
        v[j] = (i < nb2) ? g_cnt[i] : 0;
    }
    int s = v[0] + v[1] + v[2] + v[3];
    int lane = t & 31, wid = t >> 5;
    int sc = s;
    #pragma unroll
    for (int o = 1; o < 32; o <<= 1) {
        int u = __shfl_up_sync(0xFFFFFFFFu, sc, o);
        if (lane >= o) sc += u;
    }
    if (lane == 31) warp_sums[wid] = sc;
    __syncthreads();
    if (t == 0) {
        int run = 0;
        #pragma unroll
        for (int w = 0; w < 8; w++) { wbase[w] = run; run += warp_sums[w]; }
        g_bsum[blockIdx.x] = run;
    }
    __syncthreads();
    int run = wbase[wid] + (sc - s);
    #pragma unroll
    for (int j = 0; j < 4; j++) {
        int i = idx0 + j;
        if (i < nb2) g_off[i] = run;
        run += v[j];
    }
}

// scanC2: each block computes its own base (sum of preceding block sums) and adds it
__global__ void scanC2(int nb2, int nblk) {
    __shared__ int red[8];
    __shared__ int adds;
    int t = threadIdx.x;
    int b = blockIdx.x;
    int lane = t & 31, wid = t >> 5;
    int v = (t < b) ? g_bsum[t] : 0;
    #pragma unroll
    for (int o = 16; o > 0; o >>= 1) v += __shfl_down_sync(0xFFFFFFFFu, v, o);
    if (lane == 0) red[wid] = v;
    __syncthreads();
    if (t == 0) {
        int s = 0;
        #pragma unroll
        for (int w = 0; w < 8; w++) s += red[w];
        adds = s;
    }
    __syncthreads();
    int add = adds;
    int base = b * SCAN_BLK;
    #pragma unroll
    for (int j = 0; j < 4; j++) {
        int i = base + t * 4 + j;
        if (i < nb2) g_off[i] += add;
    }
}

// place: g_off doubles as cursor; after this kernel g_off[bin] == bin end.
__global__ void place_kernel(const int* __restrict__ src,
                             const int* __restrict__ dst,
                             int E, int half, int n) {
    int e = blockIdx.x * blockDim.x + threadIdx.x;
    if (e >= E) return;
    int s = __ldg(src + e);
    int d = __ldg(dst + e);
    int bin = (e >= half) ? (n + d) : d;
    int pos = atomicAdd(&g_off[bin], 1);
    g_eidx[pos] = s;
}

// One warp per bin: sum x[src] rows, write g_acc row. start = end - deg.
__global__ void gather_kernel(const float* __restrict__ x, int nb2) {
    int wid_in_blk = threadIdx.x >> 5;
    int lane = threadIdx.x & 31;
    int bin = blockIdx.x * 8 + wid_in_blk;
    if (bin >= nb2) return;
    int deg = g_cnt[bin];
    int off = g_off[bin] - deg;

    float2 a = make_float2(0.f, 0.f);
    float2 b = make_float2(0.f, 0.f);
    int i = 0;
    for (; i + 1 < deg; i += 2) {
        int s0 = __ldg(g_eidx + off + i);
        int s1 = __ldg(g_eidx + off + i + 1);
        float2 v0 = __ldg(reinterpret_cast<const float2*>(x + (size_t)s0 * D) + lane);
        float2 v1 = __ldg(reinterpret_cast<const float2*>(x + (size_t)s1 * D) + lane);
        a.x += v0.x; a.y += v0.y;
        b.x += v1.x; b.y += v1.y;
    }
    if (i < deg) {
        int s0 = __ldg(g_eidx + off + i);
        float2 v0 = __ldg(reinterpret_cast<const float2*>(x + (size_t)s0 * D) + lane);
        a.x += v0.x; a.y += v0.y;
    }
    a.x += b.x; a.y += b.y;
    reinterpret_cast<float2*>(g_acc + (size_t)bin * D)[lane] = a;
}

// ---------------------------------------------------------------------------
__device__ __forceinline__ uint32_t sptr(const void* p) {
    return (uint32_t)__cvta_generic_to_shared(p);
}
__device__ __forceinline__ void ldsm_x4(uint32_t& r0, uint32_t& r1, uint32_t& r2, uint32_t& r3,
                                        uint32_t addr) {
    asm volatile("ldmatrix.sync.aligned.m8n8.x4.shared.b16 {%0,%1,%2,%3}, [%4];"
                 : "=r"(r0), "=r"(r1), "=r"(r2), "=r"(r3) : "r"(addr));
}
__device__ __forceinline__ void ldsm_x4_t(uint32_t& r0, uint32_t& r1, uint32_t& r2, uint32_t& r3,
                                          uint32_t addr) {
    asm volatile("ldmatrix.sync.aligned.m8n8.x4.trans.shared.b16 {%0,%1,%2,%3}, [%4];"
                 : "=r"(r0), "=r"(r1), "=r"(r2), "=r"(r3) : "r"(addr));
}
__device__ __forceinline__ void mma_bf16(float* c, uint32_t a0, uint32_t a1, uint32_t a2, uint32_t a3,
                                         uint32_t b0, uint32_t b1) {
    asm volatile("mma.sync.aligned.m16n8k16.row.col.f32.bf16.bf16.f32 "
                 "{%0,%1,%2,%3}, {%4,%5,%6,%7}, {%8,%9}, {%0,%1,%2,%3};"
                 : "+f"(c[0]), "+f"(c[1]), "+f"(c[2]), "+f"(c[3])
                 : "r"(a0), "r"(a1), "r"(a2), "r"(a3), "r"(b0), "r"(b1));
}

// ---------------------------------------------------------------------------
// Tensor-core node kernel. Staging: uint4 copy of prepped weights + trunc-split U.
__global__ void node_mma_kernel(const float* __restrict__ x,
                                const float* __restrict__ r,
                                const float* __restrict__ W_R, const float* __restrict__ b_R,
                                float* __restrict__ out, int n) {
    int tid = threadIdx.x;

    if (blockIdx.x == gridDim.x - 1) {   // r_out block
        if (tid < 64) {
            float acc = b_R[tid];
            const float* wrow = W_R + tid * 64;
            #pragma unroll 8
            for (int k = 0; k < 64; k++) acc += r[k] * wrow[k];
            out[(size_t)n * D + tid] = acc;
        }
        return;
    }

    extern __shared__ __align__(16) char smraw[];
    __nv_bfloat16* WThi = (__nv_bfloat16*)smraw;            // [192][WS]
    __nv_bfloat16* WTlo = WThi + KD * WS;                   // [192][WS]
    __nv_bfloat16* Uhi  = WTlo + KD * WS;                   // [MT][US]
    __nv_bfloat16* Ulo  = Uhi + MT * US;                    // [MT][US]
    float* Ksm = (float*)(Ulo + MT * US);                   // [64] then bOs, bIs
    float* bOs = Ksm + 64;
    float* bIs = bOs + 64;
    float* cOs = bIs + 64;                                  // [64]
    float* cIs = cOs + 64;                                  // [64]

    int node0 = blockIdx.x * MT;

    // ---- stage prepped split weights: straight uint4 copy ----
    {
        const uint4* srcw = reinterpret_cast<const uint4*>(g_wt);
        uint4* dstw = reinterpret_cast<uint4*>(WThi);       // WThi|WTlo contiguous
        #pragma unroll 4
        for (int i = tid; i < (2 * KD * WS) / 8; i += 128) dstw[i] = srcw[i];
    }
    // FIX (R8 bug): block has 128 threads; copy all 192 consts with a strided loop.
    for (int i = tid; i < 192; i += 128) Ksm[i] = g_const[i];   // Ksm|bOs|bIs contiguous
    if (tid < 64) {
        int nn = node0 + tid;
        cOs[tid] = (nn < n) ? (float)g_cnt[nn] : 0.f;
        cIs[tid] = (nn < n) ? (float)g_cnt[n + nn] : 0.f;
    }

    // ---- stage U tile with truncation split: 2 threads per row ----
    {
        int nl = tid >> 1;
        int h  = tid & 1;
        int nn = node0 + nl;
        float cO = 0.f, cI = 0.f;
        if (nn < n) {
            cO = (float)g_cnt[nn];
            cI = (float)g_cnt[n + nn];
        }
        const float4* xr = reinterpret_cast<const float4*>(x + (size_t)nn * D);
        const float4* ao = reinterpret_cast<const float4*>(g_acc + (size_t)nn * D);
        const float4* ai = reinterpret_cast<const float4*>(g_acc + ((size_t)n + nn) * D);
        uint32_t* UhiR = reinterpret_cast<uint32_t*>(Uhi + nl * US);
        uint32_t* UloR = reinterpret_cast<uint32_t*>(Ulo + nl * US);
        const float4 z4 = make_float4(0.f, 0.f, 0.f, 0.f);

        #pragma unroll
        for (int q = h * 8; q < h * 8 + 8; q++) {
            float4 vx = z4, vo = z4, vi = z4;
            if (nn < n) {
                vx = __ldg(xr + q);
                vo = ao[q];
                vi = ai[q];
            }
            vo.x -= cO * vx.x; vo.y -= cO * vx.y; vo.z -= cO * vx.z; vo.w -= cO * vx.w;
            vi.x -= cI * vx.x; vi.y -= cI * vx.y; vi.z -= cI * vx.z; vi.w -= cI * vx.w;
            int k2 = q * 2;
            uint32_t hh, ll;
            tsplit2(vx.x, vx.y, hh, ll); UhiR[k2] = hh;          UloR[k2] = ll;
            tsplit2(vx.z, vx.w, hh, ll); UhiR[k2 + 1] = hh;      UloR[k2 + 1] = ll;
            tsplit2(vo.x, vo.y, hh, ll); UhiR[32 + k2] = hh;     UloR[32 + k2] = ll;
            tsplit2(vo.z, vo.w, hh, ll); UhiR[32 + k2 + 1] = hh; UloR[32 + k2 + 1] = ll;
            tsplit2(vi.x, vi.y, hh, ll); UhiR[64 + k2] = hh;     UloR[64 + k2] = ll;
            tsplit2(vi.z, vi.w, hh, ll); UhiR[64 + k2 + 1] = hh; UloR[64 + k2 + 1] = ll;
        }
    }
    __syncthreads();

    // ---- MMA mainloop ----
    int warp = tid >> 5, lane = tid & 31;
    int wr0 = warp * 16;

    float acc[8][4];
    #pragma unroll
    for (int i = 0; i < 8; i++)
        #pragma unroll
        for (int j = 0; j < 4; j++) acc[i][j] = 0.f;

    int lrow = lane & 15;
    int lcol = (lane >> 4) * 8;
    uint32_t aHiBase = sptr(Uhi + (wr0 + lrow) * US + lcol);
    uint32_t aLoBase = sptr(Ulo + (wr0 + lrow) * US + lcol);
    uint32_t bHiBase = sptr(WThi + lrow * WS + lcol);
    uint32_t bLoBase = sptr(WTlo + lrow * WS + lcol);

    for (int ks = 0; ks < KD / 16; ks++) {
        uint32_t koffA = ks * 16 * 2;
        uint32_t koffB = (uint32_t)(ks * 16 * WS) * 2;

        uint32_t ah0, ah1, ah2, ah3, al0, al1, al2, al3;
        ldsm_x4(ah0, ah1, ah2, ah3, aHiBase + koffA);
        ldsm_x4(al0, al1, al2, al3, aLoBase + koffA);

        uint32_t bh[4][4], bl[4][4];
        #pragma unroll
        for (int p = 0; p < 4; p++) {
            uint32_t cofs = (uint32_t)(p * 16) * 2;
            ldsm_x4_t(bh[p][0], bh[p][1], bh[p][2], bh[p][3], bHiBase + koffB + cofs);
            ldsm_x4_t(bl[p][0], bl[p][1], bl[p][2], bl[p][3], bLoBase + koffB + cofs);
        }

        #pragma unroll
        for (int p = 0; p < 4; p++) {
            mma_bf16(acc[2 * p],     ah0, ah1, ah2, ah3, bh[p][0], bh[p][1]);
            mma_bf16(acc[2 * p + 1], ah0, ah1, ah2, ah3, bh[p][2], bh[p][3]);
        }
        #pragma unroll
        for (int p = 0; p < 4; p++) {
            mma_bf16(acc[2 * p],     ah0, ah1, ah2, ah3, bl[p][0], bl[p][1]);
            mma_bf16(acc[2 * p + 1], ah0, ah1, ah2, ah3, bl[p][2], bl[p][3]);
        }
        #pragma unroll
        for (int p = 0; p < 4; p++) {
            mma_bf16(acc[2 * p],     al0, al1, al2, al3, bh[p][0], bh[p][1]);
            mma_bf16(acc[2 * p + 1], al0, al1, al2, al3, bh[p][2], bh[p][3]);
        }
    }

    // ---- epilogue ----
    int rl0 = wr0 + (lane >> 2);
    int rl1 = rl0 + 8;
    int nn0 = node0 + rl0;
    int nn1 = node0 + rl1;
    float cO0 = cOs[rl0], cI0 = cIs[rl0];
    float cO1 = cOs[rl1], cI1 = cIs[rl1];
    int ecol = (lane & 3) * 2;

    #pragma unroll
    for (int nt = 0; nt < 8; nt++) {
        int c = nt * 8 + ecol;
        float k0v = Ksm[c],  k1v = Ksm[c + 1];
        float bo0 = bOs[c],  bo1 = bOs[c + 1];
        float bi0 = bIs[c],  bi1 = bIs[c + 1];
        if (nn0 < n) {
            float2 o;
            o.x = acc[nt][0] + k0v + cO0 * bo0 + cI0 * bi0;
            o.y = acc[nt][1] + k1v + cO0 * bo1 + cI0 * bi1;
            *reinterpret_cast<float2*>(out + (size_t)nn0 * D + c) = o;
        }
        if (nn1 < n) {
            float2 o;
            o.x = acc[nt][2] + k0v + cO1 * bo0 + cI1 * bi0;
            o.y = acc[nt][3] + k1v + cO1 * bo1 + cI1 * bi1;
            *reinterpret_cast<float2*>(out + (size_t)nn1 * D + c) = o;
        }
    }
}

// ---------------------------------------------------------------------------
extern "C" void kernel_launch(void* const* d_in, const int* in_sizes, int n_in,
                              void* d_out, int out_size) {
    const float* x   = (const float*)d_in[0];
    const float* r   = (const float*)d_in[1];
    const int*   src = (const int*)d_in[2];
    const int*   dst = (const int*)d_in[3];
    const float* W_O = (const float*)d_in[4];
    const float* b_O = (const float*)d_in[5];
    const float* W_I = (const float*)d_in[6];
    const float* b_I = (const float*)d_in[7];
    const float* W_S = (const float*)d_in[8];
    const float* b_S = (const float*)d_in[9];
    const float* W_R = (const float*)d_in[10];
    const float* b_R = (const float*)d_in[11];
    float* out = (float*)d_out;

    int n = in_sizes[0] / D;       // 100000
    int E = in_sizes[2];           // 1200000
    int half = E / 2;
    int nb2 = 2 * n;
    int nscan = (nb2 + SCAN_BLK - 1) / SCAN_BLK;   // 196

    const int SMEM_BYTES = (2 * KD * WS + 2 * MT * US) * (int)sizeof(__nv_bfloat16)
                         + 5 * 64 * (int)sizeof(float);
    cudaFuncSetAttribute(node_mma_kernel, cudaFuncAttributeMaxDynamicSharedMemorySize, SMEM_BYTES);

    prep_kernel<<<4, 256>>>(W_O, W_I, W_S, b_O, b_I, b_S, r);
    zero_small<<<(nb2 + 255) / 256, 256>>>(nb2);
    hist_kernel<<<(E + 255) / 256, 256>>>(dst, E, half, n);
    scanA<<<nscan, 256>>>(nb2);
    scanC2<<<nscan, 256>>>(nb2, nscan);
    place_kernel<<<(E + 255) / 256, 256>>>(src, dst, E, half, n);
    gather_kernel<<<(nb2 + 7) / 8, 256>>>(x, nb2);

    int nblocks = (n + MT - 1) / MT + 1;   // +1 for r_out
    node_mma_kernel<<<nblocks, 128, SMEM_BYTES>>>(x, r, W_R, b_R, out, n);
}